// round 8
// baseline (speedup 1.0000x reference)
#include <cuda_runtime.h>

// BilinearSampler: B=16, H=256, W=256, C=32, fp32, NHWC.
//
// R7: the R3/R6 MLP attempts failed because ptxas's heuristic register
// target (32) forced load sinking / local-memory spills. Fix: declare
// __launch_bounds__(256, 2) -> 128-reg budget, write the 4-pixel body in
// straight-line scalar form, and let ptxas front-batch the 16 corner
// gathers naturally. 8 threads per pixel (one float4 each) keeps every
// corner read one coalesced 128B line. Streaming stores for the
// write-once output.

#define BS_B 16
#define BS_H 256
#define BS_W 256
#define BS_C 32
#define BS_C4 (BS_C / 4)

// Per-pixel address/weight computation (pure scalar, inlined 4x).
#define BS_PREP(i)                                                            \
    const float x##i = 0.5f * (xc##i + 1.0f) * (float)(BS_W - 1);             \
    const float y##i = 0.5f * (yc##i + 1.0f) * (float)(BS_H - 1);             \
    int x0_##i = __float2int_rd(x##i);                                        \
    int y0_##i = __float2int_rd(y##i);                                        \
    int x0c##i = min(max(x0_##i, 0), BS_W - 1);                               \
    int x1c##i = min(max(x0_##i + 1, 0), BS_W - 1);                           \
    int y0c##i = min(max(y0_##i, 0), BS_H - 1);                               \
    int y1c##i = min(max(y0_##i + 1, 0), BS_H - 1);                           \
    const float wa##i = ((float)x1c##i - x##i) * ((float)y1c##i - y##i);      \
    const float wb##i = ((float)x1c##i - x##i) * (y##i - (float)y0c##i);      \
    const float wc##i = (x##i - (float)x0c##i) * ((float)y1c##i - y##i);      \
    const float wd##i = (x##i - (float)x0c##i) * (y##i - (float)y0c##i);      \
    const unsigned bimg##i = (pix##i >> 16) * (unsigned)(BS_H * BS_W * BS_C); \
    const unsigned oa##i = bimg##i + (unsigned)(y0c##i * BS_W + x0c##i) * BS_C + co; \
    const unsigned ob##i = bimg##i + (unsigned)(y1c##i * BS_W + x0c##i) * BS_C + co; \
    const unsigned oc##i = bimg##i + (unsigned)(y0c##i * BS_W + x1c##i) * BS_C + co; \
    const unsigned od##i = bimg##i + (unsigned)(y1c##i * BS_W + x1c##i) * BS_C + co;

#define BS_LOAD(i)                                                            \
    const float4 Ia##i = __ldg((const float4*)&img[oa##i]);                   \
    const float4 Ib##i = __ldg((const float4*)&img[ob##i]);                   \
    const float4 Ic##i = __ldg((const float4*)&img[oc##i]);                   \
    const float4 Id##i = __ldg((const float4*)&img[od##i]);

#define BS_BLEND_STORE(i)                                                     \
    {                                                                         \
        float4 r;                                                             \
        r.x = wa##i * Ia##i.x + wb##i * Ib##i.x + wc##i * Ic##i.x + wd##i * Id##i.x; \
        r.y = wa##i * Ia##i.y + wb##i * Ib##i.y + wc##i * Ic##i.y + wd##i * Id##i.y; \
        r.z = wa##i * Ia##i.z + wb##i * Ib##i.z + wc##i * Ic##i.z + wd##i * Id##i.z; \
        r.w = wa##i * Ia##i.w + wb##i * Ib##i.w + wc##i * Ic##i.w + wd##i * Id##i.w; \
        __stcs((float4*)&out[pix##i * (unsigned)BS_C + co], r);               \
    }

__global__ __launch_bounds__(256, 2) void bilinear_sampler_kernel(
    const float* __restrict__ img,
    const float* __restrict__ xs,
    const float* __restrict__ ys,
    float* __restrict__ out)
{
    const unsigned total = (unsigned)BS_B * BS_H * BS_W * BS_C4; // 8,388,608
    const unsigned q     = total / 4u;                           // 2,097,152

    unsigned t = blockIdx.x * blockDim.x + threadIdx.x;
    if (t >= q) return;

    const int co = ((int)t & (BS_C4 - 1)) * 4;

    const unsigned pix0 = t >> 3;
    const unsigned pix1 = (t + q) >> 3;
    const unsigned pix2 = (t + 2u * q) >> 3;
    const unsigned pix3 = (t + 3u * q) >> 3;

    // Coordinate loads (8 independent 32-bit loads).
    const float xc0 = __ldg(&xs[pix0]);
    const float yc0 = __ldg(&ys[pix0]);
    const float xc1 = __ldg(&xs[pix1]);
    const float yc1 = __ldg(&ys[pix1]);
    const float xc2 = __ldg(&xs[pix2]);
    const float yc2 = __ldg(&ys[pix2]);
    const float xc3 = __ldg(&xs[pix3]);
    const float yc3 = __ldg(&ys[pix3]);

    BS_PREP(0)
    BS_PREP(1)
    BS_PREP(2)
    BS_PREP(3)

    // 16 corner gathers — with the 128-reg budget ptxas keeps these live
    // and front-batches the issues.
    BS_LOAD(0)
    BS_LOAD(1)
    BS_LOAD(2)
    BS_LOAD(3)

    BS_BLEND_STORE(0)
    BS_BLEND_STORE(1)
    BS_BLEND_STORE(2)
    BS_BLEND_STORE(3)
}

extern "C" void kernel_launch(void* const* d_in, const int* in_sizes, int n_in,
                              void* d_out, int out_size) {
    const float* img = (const float*)d_in[0];
    const float* xs  = (const float*)d_in[1];
    const float* ys  = (const float*)d_in[2];
    float* out = (float*)d_out;

    const unsigned total = (unsigned)BS_B * BS_H * BS_W * BS_C4;
    const unsigned q     = total / 4u;
    const int threads = 256;
    const int blocks = (int)((q + threads - 1) / threads);
    bilinear_sampler_kernel<<<blocks, threads>>>(img, xs, ys, out);
}

// round 9
// speedup vs baseline: 1.1217x; 1.1217x over previous
#include <cuda_runtime.h>

// BilinearSampler: B=16, H=256, W=256, C=32, fp32, NHWC.
//
// R8: controlled in-flight-load test. Evidence so far: perf tracks
// (warps/SM x per-thread-MLP). R2: 54x5=270 -> 53.4us. R7: 14x16=224 ->
// 70.9us. This round: 2 px/thread in straight-line form with
// __launch_bounds__(256,4) (64-reg budget) so ptxas keeps all 8 corner
// float4s live and front-batches them, at ~50% occupancy ->
// product ~300+. Coords use __ldcs (read-once, don't pollute L2);
// output uses __stcs (write-once streaming).

#define BS_B 16
#define BS_H 256
#define BS_W 256
#define BS_C 32
#define BS_C4 (BS_C / 4)

#define BS_PREP(i)                                                            \
    const float x##i = 0.5f * (xc##i + 1.0f) * (float)(BS_W - 1);             \
    const float y##i = 0.5f * (yc##i + 1.0f) * (float)(BS_H - 1);             \
    int x0_##i = __float2int_rd(x##i);                                        \
    int y0_##i = __float2int_rd(y##i);                                        \
    int x0c##i = min(max(x0_##i, 0), BS_W - 1);                               \
    int x1c##i = min(max(x0_##i + 1, 0), BS_W - 1);                           \
    int y0c##i = min(max(y0_##i, 0), BS_H - 1);                               \
    int y1c##i = min(max(y0_##i + 1, 0), BS_H - 1);                           \
    const float wa##i = ((float)x1c##i - x##i) * ((float)y1c##i - y##i);      \
    const float wb##i = ((float)x1c##i - x##i) * (y##i - (float)y0c##i);      \
    const float wc##i = (x##i - (float)x0c##i) * ((float)y1c##i - y##i);      \
    const float wd##i = (x##i - (float)x0c##i) * (y##i - (float)y0c##i);      \
    const unsigned bimg##i = (pix##i >> 16) * (unsigned)(BS_H * BS_W * BS_C); \
    const unsigned oa##i = bimg##i + (unsigned)(y0c##i * BS_W + x0c##i) * BS_C + co; \
    const unsigned ob##i = bimg##i + (unsigned)(y1c##i * BS_W + x0c##i) * BS_C + co; \
    const unsigned oc##i = bimg##i + (unsigned)(y0c##i * BS_W + x1c##i) * BS_C + co; \
    const unsigned od##i = bimg##i + (unsigned)(y1c##i * BS_W + x1c##i) * BS_C + co;

#define BS_LOAD(i)                                                            \
    const float4 Ia##i = __ldg((const float4*)&img[oa##i]);                   \
    const float4 Ib##i = __ldg((const float4*)&img[ob##i]);                   \
    const float4 Ic##i = __ldg((const float4*)&img[oc##i]);                   \
    const float4 Id##i = __ldg((const float4*)&img[od##i]);

#define BS_BLEND_STORE(i)                                                     \
    {                                                                         \
        float4 r;                                                             \
        r.x = wa##i * Ia##i.x + wb##i * Ib##i.x + wc##i * Ic##i.x + wd##i * Id##i.x; \
        r.y = wa##i * Ia##i.y + wb##i * Ib##i.y + wc##i * Ic##i.y + wd##i * Id##i.y; \
        r.z = wa##i * Ia##i.z + wb##i * Ib##i.z + wc##i * Ic##i.z + wd##i * Id##i.z; \
        r.w = wa##i * Ia##i.w + wb##i * Ib##i.w + wc##i * Ic##i.w + wd##i * Id##i.w; \
        __stcs((float4*)&out[pix##i * (unsigned)BS_C + co], r);               \
    }

__global__ __launch_bounds__(256, 4) void bilinear_sampler_kernel(
    const float* __restrict__ img,
    const float* __restrict__ xs,
    const float* __restrict__ ys,
    float* __restrict__ out)
{
    const unsigned total = (unsigned)BS_B * BS_H * BS_W * BS_C4; // 8,388,608
    const unsigned half  = total >> 1;                           // 4,194,304

    unsigned t = blockIdx.x * blockDim.x + threadIdx.x;
    if (t >= half) return;

    const int co = ((int)t & (BS_C4 - 1)) * 4;

    const unsigned pix0 = t >> 3;
    const unsigned pix1 = (t + half) >> 3;

    // Coordinate loads: read-once, streaming hint.
    const float xc0 = __ldcs(&xs[pix0]);
    const float yc0 = __ldcs(&ys[pix0]);
    const float xc1 = __ldcs(&xs[pix1]);
    const float yc1 = __ldcs(&ys[pix1]);

    BS_PREP(0)
    BS_PREP(1)

    // 8 corner gathers, all live simultaneously (64-reg budget).
    BS_LOAD(0)
    BS_LOAD(1)

    BS_BLEND_STORE(0)
    BS_BLEND_STORE(1)
}

extern "C" void kernel_launch(void* const* d_in, const int* in_sizes, int n_in,
                              void* d_out, int out_size) {
    const float* img = (const float*)d_in[0];
    const float* xs  = (const float*)d_in[1];
    const float* ys  = (const float*)d_in[2];
    float* out = (float*)d_out;

    const unsigned total = (unsigned)BS_B * BS_H * BS_W * BS_C4;
    const unsigned half  = total >> 1;
    const int threads = 256;
    const int blocks = (int)((half + threads - 1) / threads);
    bilinear_sampler_kernel<<<blocks, threads>>>(img, xs, ys, out);
}

// round 12
// speedup vs baseline: 1.2331x; 1.0993x over previous
#include <cuda_runtime.h>

// BilinearSampler: B=16, H=256, W=256, C=32, fp32, NHWC.
//
// R9: R2's structure is at the L2 (LTS) bandwidth wall (671MB through L2
// at ~12.6 TB/s = measured chip cap), which explains why every
// occupancy-vs-MLP trade (R3/R6/R7/R8) lost. This round keeps R2's exact
// shape (2 px/thread, 8 lanes/px, one coalesced 128B line per corner) and
// only raises the reg ceiling to 42 (__launch_bounds__(256,6)) so ptxas
// front-batches a few more of the 8 gathers while occupancy stays >=75%.
// Coords use __ldcs (read-once), output __stcs (write-once).

#define BS_B 16
#define BS_H 256
#define BS_W 256
#define BS_C 32
#define BS_C4 (BS_C / 4)

#define BS_PREP(i)                                                            \
    const float x##i = 0.5f * (xc##i + 1.0f) * (float)(BS_W - 1);             \
    const float y##i = 0.5f * (yc##i + 1.0f) * (float)(BS_H - 1);             \
    int x0_##i = __float2int_rd(x##i);                                        \
    int y0_##i = __float2int_rd(y##i);                                        \
    int x0c##i = min(max(x0_##i, 0), BS_W - 1);                               \
    int x1c##i = min(max(x0_##i + 1, 0), BS_W - 1);                           \
    int y0c##i = min(max(y0_##i, 0), BS_H - 1);                               \
    int y1c##i = min(max(y0_##i + 1, 0), BS_H - 1);                           \
    const float wa##i = ((float)x1c##i - x##i) * ((float)y1c##i - y##i);      \
    const float wb##i = ((float)x1c##i - x##i) * (y##i - (float)y0c##i);      \
    const float wc##i = (x##i - (float)x0c##i) * ((float)y1c##i - y##i);      \
    const float wd##i = (x##i - (float)x0c##i) * (y##i - (float)y0c##i);      \
    const unsigned bimg##i = (pix##i >> 16) * (unsigned)(BS_H * BS_W * BS_C); \
    const unsigned oa##i = bimg##i + (unsigned)(y0c##i * BS_W + x0c##i) * BS_C + co; \
    const unsigned ob##i = bimg##i + (unsigned)(y1c##i * BS_W + x0c##i) * BS_C + co; \
    const unsigned oc##i = bimg##i + (unsigned)(y0c##i * BS_W + x1c##i) * BS_C + co; \
    const unsigned od##i = bimg##i + (unsigned)(y1c##i * BS_W + x1c##i) * BS_C + co;

#define BS_LOAD(i)                                                            \
    const float4 Ia##i = __ldg((const float4*)&img[oa##i]);                   \
    const float4 Ib##i = __ldg((const float4*)&img[ob##i]);                   \
    const float4 Ic##i = __ldg((const float4*)&img[oc##i]);                   \
    const float4 Id##i = __ldg((const float4*)&img[od##i]);

#define BS_BLEND_STORE(i)                                                     \
    {                                                                         \
        float4 r;                                                             \
        r.x = wa##i * Ia##i.x + wb##i * Ib##i.x + wc##i * Ic##i.x + wd##i * Id##i.x; \
        r.y = wa##i * Ia##i.y + wb##i * Ib##i.y + wc##i * Ic##i.y + wd##i * Id##i.y; \
        r.z = wa##i * Ia##i.z + wb##i * Ib##i.z + wc##i * Ic##i.z + wd##i * Id##i.z; \
        r.w = wa##i * Ia##i.w + wb##i * Ib##i.w + wc##i * Ic##i.w + wd##i * Id##i.w; \
        __stcs((float4*)&out[pix##i * (unsigned)BS_C + co], r);               \
    }

__global__ __launch_bounds__(256, 6) void bilinear_sampler_kernel(
    const float* __restrict__ img,
    const float* __restrict__ xs,
    const float* __restrict__ ys,
    float* __restrict__ out)
{
    const unsigned total = (unsigned)BS_B * BS_H * BS_W * BS_C4; // 8,388,608
    const unsigned half  = total >> 1;                           // 4,194,304

    unsigned t = blockIdx.x * blockDim.x + threadIdx.x;
    if (t >= half) return;

    const int co = ((int)t & (BS_C4 - 1)) * 4;

    const unsigned pix0 = t >> 3;
    const unsigned pix1 = (t + half) >> 3;

    const float xc0 = __ldcs(&xs[pix0]);
    const float yc0 = __ldcs(&ys[pix0]);
    const float xc1 = __ldcs(&xs[pix1]);
    const float yc1 = __ldcs(&ys[pix1]);

    BS_PREP(0)
    BS_PREP(1)

    BS_LOAD(0)
    BS_LOAD(1)

    BS_BLEND_STORE(0)
    BS_BLEND_STORE(1)
}

extern "C" void kernel_launch(void* const* d_in, const int* in_sizes, int n_in,
                              void* d_out, int out_size) {
    const float* img = (const float*)d_in[0];
    const float* xs  = (const float*)d_in[1];
    const float* ys  = (const float*)d_in[2];
    float* out = (float*)d_out;

    const unsigned total = (unsigned)BS_B * BS_H * BS_W * BS_C4;
    const unsigned half  = total >> 1;
    const int threads = 256;
    const int blocks = (int)((half + threads - 1) / threads);
    bilinear_sampler_kernel<<<blocks, threads>>>(img, xs, ys, out);
}

// round 13
// speedup vs baseline: 1.3201x; 1.0705x over previous
#include <cuda_runtime.h>

// BilinearSampler: B=16, H=256, W=256, C=32, fp32, NHWC.
//
// FINAL (R2-champion configuration, floor-confirmed):
// The kernel is bound by L2 (LTS) bandwidth: 4x128B corner gathers +
// 128B store per pixel = ~680MB through L2 at ~12.7 TB/s = measured
// sm_103a LTS cap. Occupancy-vs-MLP sweeps (R3,R6,R7,R8,R9) all regressed
// monotonically with occupancy; the wall's best operating point is max
// warps + compiler-default 32-reg budget.
//   - 8 threads per pixel, one float4 each -> every corner read is a
//     single coalesced 128B line, store is one 128B line.
//   - 2 pixels per thread (e, e+total/2) for a little extra MLP at no
//     register cost.
//   - __ldcs coords (read-once), __stcs output (write-once) keep the
//     streamed data from displacing gather-reused image lines in L2.
//   - exact grid: no tail predicate.

#define BS_B 16
#define BS_H 256
#define BS_W 256
#define BS_C 32
#define BS_C4 (BS_C / 4)

struct Corner4 {
    const float4* pa; const float4* pb; const float4* pc; const float4* pd;
    float wa, wb, wc, wd;
};

__device__ __forceinline__ Corner4 make_corners(const float* __restrict__ img,
                                                float xsv, float ysv,
                                                unsigned pix, int co)
{
    const float x = 0.5f * (xsv + 1.0f) * (float)(BS_W - 1);
    const float y = 0.5f * (ysv + 1.0f) * (float)(BS_H - 1);

    int x0 = __float2int_rd(x);
    int y0 = __float2int_rd(y);

    int x0c = min(max(x0, 0), BS_W - 1);
    int x1c = min(max(x0 + 1, 0), BS_W - 1);
    int y0c = min(max(y0, 0), BS_H - 1);
    int y1c = min(max(y0 + 1, 0), BS_H - 1);

    const float x0f = (float)x0c, x1f = (float)x1c;
    const float y0f = (float)y0c, y1f = (float)y1c;

    Corner4 r;
    r.wa = (x1f - x) * (y1f - y);
    r.wb = (x1f - x) * (y - y0f);
    r.wc = (x - x0f) * (y1f - y);
    r.wd = (x - x0f) * (y - y0f);

    const unsigned bimg = (pix >> 16) * (unsigned)(BS_H * BS_W * BS_C);
    r.pa = (const float4*)&img[bimg + (unsigned)(y0c * BS_W + x0c) * BS_C + co];
    r.pb = (const float4*)&img[bimg + (unsigned)(y1c * BS_W + x0c) * BS_C + co];
    r.pc = (const float4*)&img[bimg + (unsigned)(y0c * BS_W + x1c) * BS_C + co];
    r.pd = (const float4*)&img[bimg + (unsigned)(y1c * BS_W + x1c) * BS_C + co];
    return r;
}

__device__ __forceinline__ float4 blend(const float4 Ia, const float4 Ib,
                                        const float4 Ic, const float4 Id,
                                        float wa, float wb, float wc, float wd)
{
    float4 r;
    r.x = wa * Ia.x + wb * Ib.x + wc * Ic.x + wd * Id.x;
    r.y = wa * Ia.y + wb * Ib.y + wc * Ic.y + wd * Id.y;
    r.z = wa * Ia.z + wb * Ib.z + wc * Ic.z + wd * Id.z;
    r.w = wa * Ia.w + wb * Ib.w + wc * Ic.w + wd * Id.w;
    return r;
}

__global__ __launch_bounds__(256) void bilinear_sampler_kernel(
    const float* __restrict__ img,   // [B,H,W,C]
    const float* __restrict__ xs,    // [B,H,W]
    const float* __restrict__ ys,    // [B,H,W]
    float* __restrict__ out)         // [B,H,W,C]
{
    const unsigned total = (unsigned)BS_B * BS_H * BS_W * BS_C4; // 8,388,608
    const unsigned half  = total >> 1;                           // 4,194,304

    const unsigned t = blockIdx.x * blockDim.x + threadIdx.x;    // grid exact

    const int co = ((int)t & (BS_C4 - 1)) * 4;
    const unsigned pix0 = t >> 3;
    const unsigned pix1 = (t + half) >> 3;

    // Coordinate loads (read-once streams), both pixels issued together.
    const float xs0 = __ldcs(&xs[pix0]);
    const float ys0 = __ldcs(&ys[pix0]);
    const float xs1 = __ldcs(&xs[pix1]);
    const float ys1 = __ldcs(&ys[pix1]);

    Corner4 k0 = make_corners(img, xs0, ys0, pix0, co);
    Corner4 k1 = make_corners(img, xs1, ys1, pix1, co);

    // 8 corner gathers.
    const float4 a0 = __ldg(k0.pa);
    const float4 b0 = __ldg(k0.pb);
    const float4 c0 = __ldg(k0.pc);
    const float4 d0 = __ldg(k0.pd);
    const float4 a1 = __ldg(k1.pa);
    const float4 b1 = __ldg(k1.pb);
    const float4 c1 = __ldg(k1.pc);
    const float4 d1 = __ldg(k1.pd);

    const float4 r0 = blend(a0, b0, c0, d0, k0.wa, k0.wb, k0.wc, k0.wd);
    const float4 r1 = blend(a1, b1, c1, d1, k1.wa, k1.wb, k1.wc, k1.wd);

    __stcs((float4*)&out[pix0 * (unsigned)BS_C + co], r0);
    __stcs((float4*)&out[pix1 * (unsigned)BS_C + co], r1);
}

extern "C" void kernel_launch(void* const* d_in, const int* in_sizes, int n_in,
                              void* d_out, int out_size) {
    const float* img = (const float*)d_in[0];
    const float* xs  = (const float*)d_in[1];
    const float* ys  = (const float*)d_in[2];
    float* out = (float*)d_out;

    const unsigned total = (unsigned)BS_B * BS_H * BS_W * BS_C4;
    const unsigned half  = total >> 1;        // 4,194,304 = 16384 * 256
    const int threads = 256;
    const int blocks  = (int)(half / threads);
    bilinear_sampler_kernel<<<blocks, threads>>>(img, xs, ys, out);
}

// round 14
// speedup vs baseline: 1.3260x; 1.0044x over previous
#include <cuda_runtime.h>

// BilinearSampler: B=16, H=256, W=256, C=32, fp32, NHWC.
//
// FINAL: L2(LTS)-bandwidth-bound at ~12 TB/s (~95% of the HW-measured
// sm_103a practical LTS cap). Operating point: max occupancy (32-reg
// budget), 8 threads/pixel (one float4 each -> every corner gather and the
// store are single coalesced 128B lines), 2 pixels/thread for cheap MLP.
// Coord loads use __ldg (coord lines are shared by ~32 pixel-groups; the
// R9/R12 __ldcs evict-first experiments each cost ~3-4us of kernel time).
// Output uses __stcs (each output line is written exactly once).
// Exact grid: 4,194,304 threads = 16384 x 256, no tail predicate.

#define BS_B 16
#define BS_H 256
#define BS_W 256
#define BS_C 32
#define BS_C4 (BS_C / 4)

struct Corner4 {
    const float4* pa; const float4* pb; const float4* pc; const float4* pd;
    float wa, wb, wc, wd;
};

__device__ __forceinline__ Corner4 make_corners(const float* __restrict__ img,
                                                float xsv, float ysv,
                                                unsigned pix, int co)
{
    const float x = 0.5f * (xsv + 1.0f) * (float)(BS_W - 1);
    const float y = 0.5f * (ysv + 1.0f) * (float)(BS_H - 1);

    int x0 = __float2int_rd(x);
    int y0 = __float2int_rd(y);

    int x0c = min(max(x0, 0), BS_W - 1);
    int x1c = min(max(x0 + 1, 0), BS_W - 1);
    int y0c = min(max(y0, 0), BS_H - 1);
    int y1c = min(max(y0 + 1, 0), BS_H - 1);

    const float x0f = (float)x0c, x1f = (float)x1c;
    const float y0f = (float)y0c, y1f = (float)y1c;

    Corner4 r;
    r.wa = (x1f - x) * (y1f - y);
    r.wb = (x1f - x) * (y - y0f);
    r.wc = (x - x0f) * (y1f - y);
    r.wd = (x - x0f) * (y - y0f);

    const unsigned bimg = (pix >> 16) * (unsigned)(BS_H * BS_W * BS_C);
    r.pa = (const float4*)&img[bimg + (unsigned)(y0c * BS_W + x0c) * BS_C + co];
    r.pb = (const float4*)&img[bimg + (unsigned)(y1c * BS_W + x0c) * BS_C + co];
    r.pc = (const float4*)&img[bimg + (unsigned)(y0c * BS_W + x1c) * BS_C + co];
    r.pd = (const float4*)&img[bimg + (unsigned)(y1c * BS_W + x1c) * BS_C + co];
    return r;
}

__device__ __forceinline__ float4 blend(const float4 Ia, const float4 Ib,
                                        const float4 Ic, const float4 Id,
                                        float wa, float wb, float wc, float wd)
{
    float4 r;
    r.x = wa * Ia.x + wb * Ib.x + wc * Ic.x + wd * Id.x;
    r.y = wa * Ia.y + wb * Ib.y + wc * Ic.y + wd * Id.y;
    r.z = wa * Ia.z + wb * Ib.z + wc * Ic.z + wd * Id.z;
    r.w = wa * Ia.w + wb * Ib.w + wc * Ic.w + wd * Id.w;
    return r;
}

__global__ __launch_bounds__(256) void bilinear_sampler_kernel(
    const float* __restrict__ img,   // [B,H,W,C]
    const float* __restrict__ xs,    // [B,H,W]
    const float* __restrict__ ys,    // [B,H,W]
    float* __restrict__ out)         // [B,H,W,C]
{
    const unsigned total = (unsigned)BS_B * BS_H * BS_W * BS_C4; // 8,388,608
    const unsigned half  = total >> 1;                           // 4,194,304

    const unsigned t = blockIdx.x * blockDim.x + threadIdx.x;    // grid exact

    const int co = ((int)t & (BS_C4 - 1)) * 4;
    const unsigned pix0 = t >> 3;
    const unsigned pix1 = (t + half) >> 3;

    // Coordinate loads: __ldg (lines are re-read by many pixel-groups;
    // keep them cached — __ldcs here measurably regresses).
    const float xs0 = __ldg(&xs[pix0]);
    const float ys0 = __ldg(&ys[pix0]);
    const float xs1 = __ldg(&xs[pix1]);
    const float ys1 = __ldg(&ys[pix1]);

    Corner4 k0 = make_corners(img, xs0, ys0, pix0, co);
    Corner4 k1 = make_corners(img, xs1, ys1, pix1, co);

    // 8 corner gathers in flight.
    const float4 a0 = __ldg(k0.pa);
    const float4 b0 = __ldg(k0.pb);
    const float4 c0 = __ldg(k0.pc);
    const float4 d0 = __ldg(k0.pd);
    const float4 a1 = __ldg(k1.pa);
    const float4 b1 = __ldg(k1.pb);
    const float4 c1 = __ldg(k1.pc);
    const float4 d1 = __ldg(k1.pd);

    const float4 r0 = blend(a0, b0, c0, d0, k0.wa, k0.wb, k0.wc, k0.wd);
    const float4 r1 = blend(a1, b1, c1, d1, k1.wa, k1.wb, k1.wc, k1.wd);

    __stcs((float4*)&out[pix0 * (unsigned)BS_C + co], r0);
    __stcs((float4*)&out[pix1 * (unsigned)BS_C + co], r1);
}

extern "C" void kernel_launch(void* const* d_in, const int* in_sizes, int n_in,
                              void* d_out, int out_size) {
    const float* img = (const float*)d_in[0];
    const float* xs  = (const float*)d_in[1];
    const float* ys  = (const float*)d_in[2];
    float* out = (float*)d_out;

    const unsigned total = (unsigned)BS_B * BS_H * BS_W * BS_C4;
    const unsigned half  = total >> 1;        // 4,194,304 = 16384 * 256
    const int threads = 256;
    const int blocks  = (int)(half / threads);
    bilinear_sampler_kernel<<<blocks, threads>>>(img, xs, ys, out);
}

// round 15
// speedup vs baseline: 1.3311x; 1.0039x over previous
#include <cuda_runtime.h>

// BilinearSampler: B=16, H=256, W=256, C=32, fp32, NHWC.
//
// R14: champion structure (L2-bandwidth-bound at ~95% of the measured
// sm_103a LTS cap; max occupancy, 8 threads/pixel, 2 px/thread, one
// coalesced 128B line per corner gather and per store). Single change vs
// R13: corner gathers use __ldcg (L2-only, no L1 allocation). Random
// gathers have ~3% cross-warp L1 hit rate but thrash the coord lines,
// which are re-read by ~32 pixel-groups each; keeping L1 for coords trims
// refetch traffic into the binding LTS pipe.
//   - coords: __ldg (L1-cached, high line reuse)
//   - gathers: __ldcg (L2 only)
//   - output: __stcs (write-once streaming)
//   - exact grid, no tail predicate

#define BS_B 16
#define BS_H 256
#define BS_W 256
#define BS_C 32
#define BS_C4 (BS_C / 4)

__device__ __forceinline__ float4 ldcg4(const float4* p) {
    return __ldcg(p);
}

struct Corner4 {
    const float4* pa; const float4* pb; const float4* pc; const float4* pd;
    float wa, wb, wc, wd;
};

__device__ __forceinline__ Corner4 make_corners(const float* __restrict__ img,
                                                float xsv, float ysv,
                                                unsigned pix, int co)
{
    const float x = 0.5f * (xsv + 1.0f) * (float)(BS_W - 1);
    const float y = 0.5f * (ysv + 1.0f) * (float)(BS_H - 1);

    int x0 = __float2int_rd(x);
    int y0 = __float2int_rd(y);

    int x0c = min(max(x0, 0), BS_W - 1);
    int x1c = min(max(x0 + 1, 0), BS_W - 1);
    int y0c = min(max(y0, 0), BS_H - 1);
    int y1c = min(max(y0 + 1, 0), BS_H - 1);

    const float x0f = (float)x0c, x1f = (float)x1c;
    const float y0f = (float)y0c, y1f = (float)y1c;

    Corner4 r;
    r.wa = (x1f - x) * (y1f - y);
    r.wb = (x1f - x) * (y - y0f);
    r.wc = (x - x0f) * (y1f - y);
    r.wd = (x - x0f) * (y - y0f);

    const unsigned bimg = (pix >> 16) * (unsigned)(BS_H * BS_W * BS_C);
    r.pa = (const float4*)&img[bimg + (unsigned)(y0c * BS_W + x0c) * BS_C + co];
    r.pb = (const float4*)&img[bimg + (unsigned)(y1c * BS_W + x0c) * BS_C + co];
    r.pc = (const float4*)&img[bimg + (unsigned)(y0c * BS_W + x1c) * BS_C + co];
    r.pd = (const float4*)&img[bimg + (unsigned)(y1c * BS_W + x1c) * BS_C + co];
    return r;
}

__device__ __forceinline__ float4 blend(const float4 Ia, const float4 Ib,
                                        const float4 Ic, const float4 Id,
                                        float wa, float wb, float wc, float wd)
{
    float4 r;
    r.x = wa * Ia.x + wb * Ib.x + wc * Ic.x + wd * Id.x;
    r.y = wa * Ia.y + wb * Ib.y + wc * Ic.y + wd * Id.y;
    r.z = wa * Ia.z + wb * Ib.z + wc * Ic.z + wd * Id.z;
    r.w = wa * Ia.w + wb * Ib.w + wc * Ic.w + wd * Id.w;
    return r;
}

__global__ __launch_bounds__(256) void bilinear_sampler_kernel(
    const float* __restrict__ img,   // [B,H,W,C]
    const float* __restrict__ xs,    // [B,H,W]
    const float* __restrict__ ys,    // [B,H,W]
    float* __restrict__ out)         // [B,H,W,C]
{
    const unsigned total = (unsigned)BS_B * BS_H * BS_W * BS_C4; // 8,388,608
    const unsigned half  = total >> 1;                           // 4,194,304

    const unsigned t = blockIdx.x * blockDim.x + threadIdx.x;    // grid exact

    const int co = ((int)t & (BS_C4 - 1)) * 4;
    const unsigned pix0 = t >> 3;
    const unsigned pix1 = (t + half) >> 3;

    // Coordinate loads: L1-cached (high cross-warp line reuse).
    const float xs0 = __ldg(&xs[pix0]);
    const float ys0 = __ldg(&ys[pix0]);
    const float xs1 = __ldg(&xs[pix1]);
    const float ys1 = __ldg(&ys[pix1]);

    Corner4 k0 = make_corners(img, xs0, ys0, pix0, co);
    Corner4 k1 = make_corners(img, xs1, ys1, pix1, co);

    // 8 corner gathers, L2-only (don't thrash L1 coord lines).
    const float4 a0 = ldcg4(k0.pa);
    const float4 b0 = ldcg4(k0.pb);
    const float4 c0 = ldcg4(k0.pc);
    const float4 d0 = ldcg4(k0.pd);
    const float4 a1 = ldcg4(k1.pa);
    const float4 b1 = ldcg4(k1.pb);
    const float4 c1 = ldcg4(k1.pc);
    const float4 d1 = ldcg4(k1.pd);

    const float4 r0 = blend(a0, b0, c0, d0, k0.wa, k0.wb, k0.wc, k0.wd);
    const float4 r1 = blend(a1, b1, c1, d1, k1.wa, k1.wb, k1.wc, k1.wd);

    __stcs((float4*)&out[pix0 * (unsigned)BS_C + co], r0);
    __stcs((float4*)&out[pix1 * (unsigned)BS_C + co], r1);
}

extern "C" void kernel_launch(void* const* d_in, const int* in_sizes, int n_in,
                              void* d_out, int out_size) {
    const float* img = (const float*)d_in[0];
    const float* xs  = (const float*)d_in[1];
    const float* ys  = (const float*)d_in[2];
    float* out = (float*)d_out;

    const unsigned total = (unsigned)BS_B * BS_H * BS_W * BS_C4;
    const unsigned half  = total >> 1;        // 4,194,304 = 16384 * 256
    const int threads = 256;
    const int blocks  = (int)(half / threads);
    bilinear_sampler_kernel<<<blocks, threads>>>(img, xs, ys, out);
}

// round 17
// speedup vs baseline: 1.3676x; 1.0274x over previous
#include <cuda_runtime.h>

// BilinearSampler: B=16, H=256, W=256, C=32, fp32, NHWC.
//
// R15: champion (R14) + adjacent-pixel pairing. Structure is
// L2-bandwidth-bound at ~95% of the measured sm_103a LTS cap:
//   - 8 threads per pixel, one float4 each -> every corner gather and
//     store is a single coalesced 128B line
//   - 2 pixels per thread, now ADJACENT (2g, 2g+1): a warp's 8 stores
//     form one contiguous 1KB span (better DRAM write efficiency) and the
//     pair's coord loads share one L1 line
//   - coords: __ldg (L1-cached, high cross-group line reuse)
//   - gathers: __ldcg (L2-only; don't thrash L1 coord lines)
//   - output: __stcs (write-once streaming)
//   - default 32-reg budget, max occupancy, exact grid

#define BS_B 16
#define BS_H 256
#define BS_W 256
#define BS_C 32
#define BS_C4 (BS_C / 4)

__device__ __forceinline__ float4 ldcg4(const float4* p) {
    return __ldcg(p);
}

struct Corner4 {
    const float4* pa; const float4* pb; const float4* pc; const float4* pd;
    float wa, wb, wc, wd;
};

__device__ __forceinline__ Corner4 make_corners(const float* __restrict__ img,
                                                float xsv, float ysv,
                                                unsigned pix, int co)
{
    const float x = 0.5f * (xsv + 1.0f) * (float)(BS_W - 1);
    const float y = 0.5f * (ysv + 1.0f) * (float)(BS_H - 1);

    int x0 = __float2int_rd(x);
    int y0 = __float2int_rd(y);

    int x0c = min(max(x0, 0), BS_W - 1);
    int x1c = min(max(x0 + 1, 0), BS_W - 1);
    int y0c = min(max(y0, 0), BS_H - 1);
    int y1c = min(max(y0 + 1, 0), BS_H - 1);

    const float x0f = (float)x0c, x1f = (float)x1c;
    const float y0f = (float)y0c, y1f = (float)y1c;

    Corner4 r;
    r.wa = (x1f - x) * (y1f - y);
    r.wb = (x1f - x) * (y - y0f);
    r.wc = (x - x0f) * (y1f - y);
    r.wd = (x - x0f) * (y - y0f);

    const unsigned bimg = (pix >> 16) * (unsigned)(BS_H * BS_W * BS_C);
    r.pa = (const float4*)&img[bimg + (unsigned)(y0c * BS_W + x0c) * BS_C + co];
    r.pb = (const float4*)&img[bimg + (unsigned)(y1c * BS_W + x0c) * BS_C + co];
    r.pc = (const float4*)&img[bimg + (unsigned)(y0c * BS_W + x1c) * BS_C + co];
    r.pd = (const float4*)&img[bimg + (unsigned)(y1c * BS_W + x1c) * BS_C + co];
    return r;
}

__device__ __forceinline__ float4 blend(const float4 Ia, const float4 Ib,
                                        const float4 Ic, const float4 Id,
                                        float wa, float wb, float wc, float wd)
{
    float4 r;
    r.x = wa * Ia.x + wb * Ib.x + wc * Ic.x + wd * Id.x;
    r.y = wa * Ia.y + wb * Ib.y + wc * Ic.y + wd * Id.y;
    r.z = wa * Ia.z + wb * Ib.z + wc * Ic.z + wd * Id.z;
    r.w = wa * Ia.w + wb * Ib.w + wc * Ic.w + wd * Id.w;
    return r;
}

__global__ __launch_bounds__(256) void bilinear_sampler_kernel(
    const float* __restrict__ img,   // [B,H,W,C]
    const float* __restrict__ xs,    // [B,H,W]
    const float* __restrict__ ys,    // [B,H,W]
    float* __restrict__ out)         // [B,H,W,C]
{
    const unsigned t = blockIdx.x * blockDim.x + threadIdx.x;    // grid exact

    const int      co   = ((int)t & (BS_C4 - 1)) * 4;
    const unsigned g    = t >> 3;          // pixel-pair group id
    const unsigned pix0 = g * 2u;
    const unsigned pix1 = pix0 + 1u;

    // Coordinate loads: adjacent elements, same L1 line per pair.
    const float xs0 = __ldg(&xs[pix0]);
    const float ys0 = __ldg(&ys[pix0]);
    const float xs1 = __ldg(&xs[pix1]);
    const float ys1 = __ldg(&ys[pix1]);

    Corner4 k0 = make_corners(img, xs0, ys0, pix0, co);
    Corner4 k1 = make_corners(img, xs1, ys1, pix1, co);

    // 8 corner gathers, L2-only.
    const float4 a0 = ldcg4(k0.pa);
    const float4 b0 = ldcg4(k0.pb);
    const float4 c0 = ldcg4(k0.pc);
    const float4 d0 = ldcg4(k0.pd);
    const float4 a1 = ldcg4(k1.pa);
    const float4 b1 = ldcg4(k1.pb);
    const float4 c1 = ldcg4(k1.pc);
    const float4 d1 = ldcg4(k1.pd);

    const float4 r0 = blend(a0, b0, c0, d0, k0.wa, k0.wb, k0.wc, k0.wd);
    const float4 r1 = blend(a1, b1, c1, d1, k1.wa, k1.wb, k1.wc, k1.wd);

    // A warp's stores cover 8 consecutive pixels = 1KB contiguous.
    __stcs((float4*)&out[pix0 * (unsigned)BS_C + co], r0);
    __stcs((float4*)&out[pix1 * (unsigned)BS_C + co], r1);
}

extern "C" void kernel_launch(void* const* d_in, const int* in_sizes, int n_in,
                              void* d_out, int out_size) {
    const float* img = (const float*)d_in[0];
    const float* xs  = (const float*)d_in[1];
    const float* ys  = (const float*)d_in[2];
    float* out = (float*)d_out;

    const unsigned total = (unsigned)BS_B * BS_H * BS_W * BS_C4; // 8,388,608
    const unsigned half  = total >> 1;        // 4,194,304 = 16384 * 256
    const int threads = 256;
    const int blocks  = (int)(half / threads);
    bilinear_sampler_kernel<<<blocks, threads>>>(img, xs, ys, out);
}